// round 15
// baseline (speedup 1.0000x reference)
#include <cuda_runtime.h>
#include <cuda_fp16.h>
#include <cstdint>
#include <float.h>

#define NG 5
#define NB 131072
#define NK 512
#define ND 64
#define CTA 256
#define XBLK (NB / CTA)          // 512 (1 row per thread)
#define NCTAS (NG * XBLK)        // 2560
#define SC2 0.00390625f          // 2/512

__device__ double g_loss_sum[NG];
__device__ unsigned int g_done = 0;

__device__ __forceinline__ __half2 H2(uint32_t u) { return *(__half2*)&u; }
__device__ __forceinline__ float PACK(float s, int k) {
    return __uint_as_float((__float_as_uint(s) & 0xFFFFFE00u) | (uint32_t)k);
}

// Exact distance: validated fp32 sequential-d fma chain (x from global/L1)
__device__ __forceinline__ float exact_dist(const float4* __restrict__ xr,
                                            const float4* __restrict__ ck,
                                            float xsq, float esqk) {
    float cr = 0.f;
    #pragma unroll
    for (int i = 0; i < 16; i++) {
        float4 v = ck[i];
        float4 x = xr[i];
        cr = fmaf(x.x, v.x, cr);
        cr = fmaf(x.y, v.y, cr);
        cr = fmaf(x.z, v.z, cr);
        cr = fmaf(x.w, v.w, cr);
    }
    return (xsq + esqk) - 2.0f * cr;
}

__global__ __launch_bounds__(CTA, 3) void vq_h3_kernel(
    const float* __restrict__ feat,   // [G,B,D]
    const float* __restrict__ cb,     // [G,K,D]
    float* __restrict__ out_q,        // [G,B,D]
    float* __restrict__ out_loss,     // [G+1]
    float* __restrict__ out_idx,      // [G,B] as float
    int write_q, int write_loss, int write_idx)
{
    extern __shared__ char smem[];
    uint32_t* cp  = (uint32_t*)smem;               // [512][32] half2 (512c_d,512c_{d+1})
    float*    esq = (float*)(smem + NK * 32 * 4);  // [512]
    float*    red = esq + NK;                      // [8]

    const int tid = threadIdx.x;
    const int g = blockIdx.y;
    const float* cbg = cb + (size_t)g * NK * ND;
    const size_t gNB = (size_t)g * NB;

    // ---- Stage codebook (2 cw/thread): half2 pairs of 512*c; exact e_sq ----
    #pragma unroll
    for (int s2 = 0; s2 < 2; s2++) {
        const int k = tid + s2 * CTA;
        const float4* cpg = (const float4*)(cbg + (size_t)k * ND);
        uint32_t* dst = cp + k * 32;
        float acc = 0.f;
        #pragma unroll
        for (int i = 0; i < 16; i++) {
            float4 v = cpg[i];
            acc = fmaf(v.x, v.x, acc);
            acc = fmaf(v.y, v.y, acc);
            acc = fmaf(v.z, v.z, acc);
            acc = fmaf(v.w, v.w, acc);
            __half2 h0 = __floats2half2_rn(v.x * 512.f, v.y * 512.f);
            __half2 h1 = __floats2half2_rn(v.z * 512.f, v.w * 512.f);
            dst[2 * i]     = *(uint32_t*)&h0;
            dst[2 * i + 1] = *(uint32_t*)&h1;
        }
        esq[k] = acc;
    }
    __syncthreads();

    // ---- Load row, pack (d,d+1) half2, exact x_sq (validated chain) ----
    const int row = blockIdx.x * CTA + tid;
    __half2 xh[32];
    float xsq = 0.f;
    {
        const float4* xp = (const float4*)(feat + (gNB + row) * ND);
        #pragma unroll
        for (int i = 0; i < 16; i++) {
            float4 a = xp[i];
            xsq = fmaf(a.x, a.x, xsq);
            xsq = fmaf(a.y, a.y, xsq);
            xsq = fmaf(a.z, a.z, xsq);
            xsq = fmaf(a.w, a.w, xsq);
            xh[2 * i]     = __floats2half2_rn(a.x, a.y);
            xh[2 * i + 1] = __floats2half2_rn(a.z, a.w);
        }
    }
    // statistical eps (R11-validated) + mantissa-packing margin (R12-validated)
    const float eps = 1.526e-5f * __fsqrt_rn(11.5f * xsq) + 1.8e-5f;

    // ---- HFMA2 filter: 4 codewords/block; packed top-3 (score|k) ----
    float t0 = FLT_MAX, t1 = FLT_MAX, t2 = FLT_MAX;
    #define INS3(p)                                                            \
    if ((p) < t2) {                                                            \
        if ((p) < t0)      { t2 = t1; t1 = t0; t0 = (p); }                     \
        else if ((p) < t1) { t2 = t1; t1 = (p); }                              \
        else               { t2 = (p); }                                       \
    }

    #pragma unroll 1
    for (int kb = 0; kb < NK / 4; kb++) {
        const int k0 = kb * 4;
        const uint4* p0 = (const uint4*)(cp + (k0 + 0) * 32);
        const uint4* p1 = (const uint4*)(cp + (k0 + 1) * 32);
        const uint4* p2 = (const uint4*)(cp + (k0 + 2) * 32);
        const uint4* p3 = (const uint4*)(cp + (k0 + 3) * 32);
        __half2 z = __float2half2_rn(0.f);
        __half2 a0 = z, a1 = z, a2 = z, a3 = z;
        #pragma unroll
        for (int c = 0; c < 8; c++) {
            uint4 u0 = p0[c], u1 = p1[c], u2 = p2[c], u3 = p3[c];
            __half2 x0 = xh[4 * c + 0], x1 = xh[4 * c + 1];
            __half2 x2 = xh[4 * c + 2], x3 = xh[4 * c + 3];
            a0 = __hfma2(H2(u0.x), x0, a0);
            a1 = __hfma2(H2(u1.x), x0, a1);
            a2 = __hfma2(H2(u2.x), x0, a2);
            a3 = __hfma2(H2(u3.x), x0, a3);
            a0 = __hfma2(H2(u0.y), x1, a0);
            a1 = __hfma2(H2(u1.y), x1, a1);
            a2 = __hfma2(H2(u2.y), x1, a2);
            a3 = __hfma2(H2(u3.y), x1, a3);
            a0 = __hfma2(H2(u0.z), x2, a0);
            a1 = __hfma2(H2(u1.z), x2, a1);
            a2 = __hfma2(H2(u2.z), x2, a2);
            a3 = __hfma2(H2(u3.z), x2, a3);
            a0 = __hfma2(H2(u0.w), x3, a0);
            a1 = __hfma2(H2(u1.w), x3, a1);
            a2 = __hfma2(H2(u2.w), x3, a2);
            a3 = __hfma2(H2(u3.w), x3, a3);
        }
        float s, p;
        s = fmaf(-(__low2float(a0) + __high2float(a0)), SC2, esq[k0 + 0]);
        p = PACK(s, k0 + 0); INS3(p)
        s = fmaf(-(__low2float(a1) + __high2float(a1)), SC2, esq[k0 + 1]);
        p = PACK(s, k0 + 1); INS3(p)
        s = fmaf(-(__low2float(a2) + __high2float(a2)), SC2, esq[k0 + 2]);
        p = PACK(s, k0 + 2); INS3(p)
        s = fmaf(-(__low2float(a3) + __high2float(a3)), SC2, esq[k0 + 3]);
        p = PACK(s, k0 + 3); INS3(p)
    }
    #undef INS3

    // ---- Selection (x reloaded from global; L1-hot) ----
    const float4* xr = (const float4*)(feat + (gNB + row) * ND);
    int bk = (int)(__float_as_uint(t0) & 511u);
    const float th = t0 + eps;
    if (t1 <= th) {
        if (t2 <= th) {
            // provable overflow: full exact scan (rare)
            float best = FLT_MAX;
            bk = 0;
            for (int k = 0; k < NK; k++) {
                float dk = exact_dist(xr, (const float4*)(cbg + (size_t)k * ND),
                                      xsq, esq[k]);
                if (dk < best || (dk == best && k < bk)) { best = dk; bk = k; }
            }
        } else {
            const int ka  = (int)(__float_as_uint(t0) & 511u);
            const int kb2 = (int)(__float_as_uint(t1) & 511u);
            float da = exact_dist(xr, (const float4*)(cbg + (size_t)ka * ND),
                                  xsq, esq[ka]);
            float db = exact_dist(xr, (const float4*)(cbg + (size_t)kb2 * ND),
                                  xsq, esq[kb2]);
            // reference first-min tie-break
            if (db < da || (db == da && kb2 < ka)) bk = kb2; else bk = ka;
        }
    }

    // ---- Outputs: quantized_st = x + (q - x), index, loss partial ----
    float lsum = 0.f;
    {
        const float4* qp = (const float4*)(cbg + (size_t)bk * ND);
        float4* oq = (float4*)(out_q + (gNB + row) * ND);
        #pragma unroll
        for (int i = 0; i < 16; i++) {
            float4 qv = qp[i], fv = xr[i];
            float dx0 = qv.x - fv.x, dx1 = qv.y - fv.y;
            float dx2 = qv.z - fv.z, dx3 = qv.w - fv.w;
            lsum = fmaf(dx0, dx0, lsum);
            lsum = fmaf(dx1, dx1, lsum);
            lsum = fmaf(dx2, dx2, lsum);
            lsum = fmaf(dx3, dx3, lsum);
            if (write_q)
                oq[i] = make_float4(fv.x + dx0, fv.y + dx1, fv.z + dx2, fv.w + dx3);
        }
    }
    if (write_idx) out_idx[gNB + row] = (float)bk;

    // ---- Loss: warp shuffle -> shared -> double atomic; last CTA finalizes ----
    #pragma unroll
    for (int off = 16; off > 0; off >>= 1)
        lsum += __shfl_xor_sync(0xFFFFFFFFu, lsum, off);
    if ((tid & 31) == 0) red[tid >> 5] = lsum;
    __syncthreads();
    if (tid == 0) {
        double s = 0.0;
        #pragma unroll
        for (int w = 0; w < CTA / 32; w++) s += (double)red[w];
        atomicAdd(&g_loss_sum[g], s);
        __threadfence();
        unsigned int t = atomicAdd(&g_done, 1u);
        if (t == NCTAS - 1) {
            __threadfence();
            if (write_loss) {
                const double inv = 1.25 / ((double)NB * (double)ND);
                float tot = 0.f;
                for (int g2 = 0; g2 < NG; g2++) {
                    float pl = (float)(g_loss_sum[g2] * inv);
                    out_loss[g2] = pl;
                    tot += pl;
                }
                out_loss[NG] = tot;
            }
            for (int g2 = 0; g2 < NG; g2++) g_loss_sum[g2] = 0.0;
            g_done = 0;
        }
    }
}

extern "C" void kernel_launch(void* const* d_in, const int* in_sizes, int n_in,
                              void* d_out, int out_size) {
    const float* feat = (const float*)d_in[0];
    const float* cb   = (const float*)d_in[1];
    if (n_in >= 2 && in_sizes[0] == NG * NK * ND) {
        const float* t = feat; feat = cb; cb = t;
    }
    float* out = (float*)d_out;

    const long long q_elems   = (long long)NG * NB * ND;
    const long long idx_elems = (long long)NG * NB;
    const long long full_sz   = q_elems + NG + 1 + idx_elems;
    const int write_q    = ((long long)out_size >= q_elems);
    const int write_loss = ((long long)out_size >= q_elems + NG + 1);
    const int write_idx  = ((long long)out_size >= full_sz);

    const int smem_bytes = NK * 32 * 4 + NK * 4 + 32;   // 67,616 B -> 3 CTAs/SM
    cudaFuncSetAttribute(vq_h3_kernel,
                         cudaFuncAttributeMaxDynamicSharedMemorySize, smem_bytes);

    dim3 grid(XBLK, NG);
    float* out_loss = out + q_elems;
    float* out_idx  = out + q_elems + NG + 1;
    vq_h3_kernel<<<grid, CTA, smem_bytes>>>(feat, cb, out, out_loss, out_idx,
                                            write_q, write_loss, write_idx);
}

// round 16
// speedup vs baseline: 1.0193x; 1.0193x over previous
#include <cuda_runtime.h>
#include <cuda_fp16.h>
#include <cstdint>
#include <float.h>

#define NG 5
#define NB 131072
#define NK 512
#define ND 64
#define CTA 256
#define RPC 512                  // rows per CTA (2 per thread)
#define XBLK (NB / RPC)          // 256
#define NCTAS (NG * XBLK)        // 1280
#define SC2 0.00390625f          // 2/512

__device__ double g_loss_sum[NG];
__device__ unsigned int g_done = 0;

__device__ __forceinline__ __half2 H2(uint32_t u) { return *(__half2*)&u; }
__device__ __forceinline__ float PACK(float s, int k) {
    return __uint_as_float((__float_as_uint(s) & 0xFFFFFE00u) | (uint32_t)k);
}

// Exact distance: validated fp32 sequential-d fma chain (x loaded from global/L1)
__device__ __forceinline__ float exact_dist(const float4* __restrict__ xr,
                                            const float4* __restrict__ ck,
                                            float xsq, float esqk) {
    float cr = 0.f;
    #pragma unroll
    for (int i = 0; i < 16; i++) {
        float4 v = ck[i];
        float4 x = xr[i];
        cr = fmaf(x.x, v.x, cr);
        cr = fmaf(x.y, v.y, cr);
        cr = fmaf(x.z, v.z, cr);
        cr = fmaf(x.w, v.w, cr);
    }
    return (xsq + esqk) - 2.0f * cr;
}

__global__ __launch_bounds__(CTA, 1) void vq_h2r2b_kernel(
    const float* __restrict__ feat,   // [G,B,D]
    const float* __restrict__ cb,     // [G,K,D]
    float* __restrict__ out_q,        // [G,B,D]
    float* __restrict__ out_loss,     // [G+1]
    float* __restrict__ out_idx,      // [G,B] as float
    int write_q, int write_loss, int write_idx)
{
    extern __shared__ char smem[];
    uint32_t* cp  = (uint32_t*)smem;               // [512][32] half2 (512c_d,512c_{d+1})
    float*    esq = (float*)(smem + NK * 32 * 4);  // [512]
    float*    red = esq + NK;                      // [8]

    const int tid = threadIdx.x;
    const int g = blockIdx.y;
    const float* cbg = cb + (size_t)g * NK * ND;
    const size_t gNB = (size_t)g * NB;

    // ---- Stage codebook (2 cw/thread): half2 pairs of 512*c; exact e_sq ----
    #pragma unroll
    for (int s2 = 0; s2 < 2; s2++) {
        const int k = tid + s2 * CTA;
        const float4* cpg = (const float4*)(cbg + (size_t)k * ND);
        uint32_t* dst = cp + k * 32;
        float acc = 0.f;
        #pragma unroll
        for (int i = 0; i < 16; i++) {
            float4 v = cpg[i];
            acc = fmaf(v.x, v.x, acc);
            acc = fmaf(v.y, v.y, acc);
            acc = fmaf(v.z, v.z, acc);
            acc = fmaf(v.w, v.w, acc);
            __half2 h0 = __floats2half2_rn(v.x * 512.f, v.y * 512.f);
            __half2 h1 = __floats2half2_rn(v.z * 512.f, v.w * 512.f);
            dst[2 * i]     = *(uint32_t*)&h0;
            dst[2 * i + 1] = *(uint32_t*)&h1;
        }
        esq[k] = acc;
    }
    __syncthreads();

    // ---- Load 2 rows, pack (d,d+1) half2, exact x_sq per row ----
    const int row0 = blockIdx.x * RPC + tid;   // row1 = row0 + CTA
    __half2 xa[32], xb[32];
    float xsq0 = 0.f, xsq1 = 0.f;
    {
        const float4* x0p = (const float4*)(feat + (gNB + row0) * ND);
        const float4* x1p = (const float4*)(feat + (gNB + row0 + CTA) * ND);
        #pragma unroll
        for (int i = 0; i < 16; i++) {
            float4 a = x0p[i];
            float4 b = x1p[i];
            xsq0 = fmaf(a.x, a.x, xsq0); xsq0 = fmaf(a.y, a.y, xsq0);
            xsq0 = fmaf(a.z, a.z, xsq0); xsq0 = fmaf(a.w, a.w, xsq0);
            xsq1 = fmaf(b.x, b.x, xsq1); xsq1 = fmaf(b.y, b.y, xsq1);
            xsq1 = fmaf(b.z, b.z, xsq1); xsq1 = fmaf(b.w, b.w, xsq1);
            xa[2 * i]     = __floats2half2_rn(a.x, a.y);
            xa[2 * i + 1] = __floats2half2_rn(a.z, a.w);
            xb[2 * i]     = __floats2half2_rn(b.x, b.y);
            xb[2 * i + 1] = __floats2half2_rn(b.z, b.w);
        }
    }
    // statistical eps (R11-validated) + mantissa-packing margin (R12-validated)
    const float eps0 = 1.526e-5f * __fsqrt_rn(11.5f * xsq0) + 1.8e-5f;
    const float eps1 = 1.526e-5f * __fsqrt_rn(11.5f * xsq1) + 1.8e-5f;

    // ---- HFMA2 filter: 4 cw x 2 rows per block; packed top-3 per row ----
    float t00 = FLT_MAX, t01 = FLT_MAX, t02 = FLT_MAX;   // row0 (score|k packed)
    float t10 = FLT_MAX, t11 = FLT_MAX, t12 = FLT_MAX;   // row1

    #define INS3(p, T0, T1, T2)                                                \
    if ((p) < T2) {                                                            \
        if ((p) < T0)      { T2 = T1; T1 = T0; T0 = (p); }                     \
        else if ((p) < T1) { T2 = T1; T1 = (p); }                              \
        else               { T2 = (p); }                                       \
    }

    #pragma unroll 1
    for (int kb = 0; kb < NK / 4; kb++) {
        const int k0 = kb * 4;
        const uint4* p0 = (const uint4*)(cp + (k0 + 0) * 32);
        const uint4* p1 = (const uint4*)(cp + (k0 + 1) * 32);
        const uint4* p2 = (const uint4*)(cp + (k0 + 2) * 32);
        const uint4* p3 = (const uint4*)(cp + (k0 + 3) * 32);
        __half2 z = __float2half2_rn(0.f);
        __half2 a00 = z, a01 = z, a02 = z, a03 = z;   // row0, cw 0..3
        __half2 a10 = z, a11 = z, a12 = z, a13 = z;   // row1
        #pragma unroll
        for (int c = 0; c < 8; c++) {
            uint4 u0 = p0[c], u1 = p1[c], u2 = p2[c], u3 = p3[c];
            __half2 xA, xB;
            #define STEP(W)                                                    \
                a00 = __hfma2(H2(u0.W), xA, a00);                              \
                a01 = __hfma2(H2(u1.W), xA, a01);                              \
                a02 = __hfma2(H2(u2.W), xA, a02);                              \
                a03 = __hfma2(H2(u3.W), xA, a03);                              \
                a10 = __hfma2(H2(u0.W), xB, a10);                              \
                a11 = __hfma2(H2(u1.W), xB, a11);                              \
                a12 = __hfma2(H2(u2.W), xB, a12);                              \
                a13 = __hfma2(H2(u3.W), xB, a13);
            xA = xa[4 * c + 0]; xB = xb[4 * c + 0]; STEP(x)
            xA = xa[4 * c + 1]; xB = xb[4 * c + 1]; STEP(y)
            xA = xa[4 * c + 2]; xB = xb[4 * c + 2]; STEP(z)
            xA = xa[4 * c + 3]; xB = xb[4 * c + 3]; STEP(w)
            #undef STEP
        }
        const float e0 = esq[k0], e1 = esq[k0 + 1], e2 = esq[k0 + 2], e3 = esq[k0 + 3];
        #define SCORE(ACC, E) fmaf(-(__low2float(ACC) + __high2float(ACC)), SC2, (E))
        float s, p;
        s = SCORE(a00, e0); p = PACK(s, k0 + 0); INS3(p, t00, t01, t02)
        s = SCORE(a01, e1); p = PACK(s, k0 + 1); INS3(p, t00, t01, t02)
        s = SCORE(a02, e2); p = PACK(s, k0 + 2); INS3(p, t00, t01, t02)
        s = SCORE(a03, e3); p = PACK(s, k0 + 3); INS3(p, t00, t01, t02)
        s = SCORE(a10, e0); p = PACK(s, k0 + 0); INS3(p, t10, t11, t12)
        s = SCORE(a11, e1); p = PACK(s, k0 + 1); INS3(p, t10, t11, t12)
        s = SCORE(a12, e2); p = PACK(s, k0 + 2); INS3(p, t10, t11, t12)
        s = SCORE(a13, e3); p = PACK(s, k0 + 3); INS3(p, t10, t11, t12)
        #undef SCORE
    }
    #undef INS3

    // ---- Selection + outputs per row (x reloaded from global; L1-hot) ----
    float lsum = 0.f;
    #pragma unroll 1
    for (int r = 0; r < 2; r++) {
        const int row = row0 + r * CTA;
        const float4* xr = (const float4*)(feat + (gNB + row) * ND);
        const float xsq = r ? xsq1 : xsq0;
        const float eps = r ? eps1 : eps0;
        const float v0 = r ? t10 : t00;
        const float v1 = r ? t11 : t01;
        const float v2 = r ? t12 : t02;
        const float th = v0 + eps;

        int bk = (int)(__float_as_uint(v0) & 511u);
        if (v1 <= th) {
            float best = FLT_MAX;
            if (v2 <= th) {
                // provable overflow: full exact scan (rare)
                bk = 0;
                for (int k = 0; k < NK; k++) {
                    float dk = exact_dist(xr, (const float4*)(cbg + (size_t)k * ND),
                                          xsq, esq[k]);
                    if (dk < best || (dk == best && k < bk)) { best = dk; bk = k; }
                }
            } else {
                const int ka  = (int)(__float_as_uint(v0) & 511u);
                const int kb2 = (int)(__float_as_uint(v1) & 511u);
                float da = exact_dist(xr, (const float4*)(cbg + (size_t)ka * ND),
                                      xsq, esq[ka]);
                float db = exact_dist(xr, (const float4*)(cbg + (size_t)kb2 * ND),
                                      xsq, esq[kb2]);
                // reference first-min tie-break
                if (db < da || (db == da && kb2 < ka)) bk = kb2; else bk = ka;
            }
        }

        const float4* qp = (const float4*)(cbg + (size_t)bk * ND);
        float4* oq = (float4*)(out_q + (gNB + row) * ND);
        #pragma unroll
        for (int i = 0; i < 16; i++) {
            float4 qv = qp[i], fv = xr[i];
            float dx0 = qv.x - fv.x, dx1 = qv.y - fv.y;
            float dx2 = qv.z - fv.z, dx3 = qv.w - fv.w;
            lsum = fmaf(dx0, dx0, lsum);
            lsum = fmaf(dx1, dx1, lsum);
            lsum = fmaf(dx2, dx2, lsum);
            lsum = fmaf(dx3, dx3, lsum);
            if (write_q)
                oq[i] = make_float4(fv.x + dx0, fv.y + dx1, fv.z + dx2, fv.w + dx3);
        }
        if (write_idx) out_idx[gNB + row] = (float)bk;
    }

    // ---- Loss: warp shuffle -> shared -> double atomic; last CTA finalizes ----
    #pragma unroll
    for (int off = 16; off > 0; off >>= 1)
        lsum += __shfl_xor_sync(0xFFFFFFFFu, lsum, off);
    if ((tid & 31) == 0) red[tid >> 5] = lsum;
    __syncthreads();
    if (tid == 0) {
        double s = 0.0;
        #pragma unroll
        for (int w = 0; w < CTA / 32; w++) s += (double)red[w];
        atomicAdd(&g_loss_sum[g], s);
        __threadfence();
        unsigned int t = atomicAdd(&g_done, 1u);
        if (t == NCTAS - 1) {
            __threadfence();
            if (write_loss) {
                const double inv = 1.25 / ((double)NB * (double)ND);
                float tot = 0.f;
                for (int g2 = 0; g2 < NG; g2++) {
                    float pl = (float)(g_loss_sum[g2] * inv);
                    out_loss[g2] = pl;
                    tot += pl;
                }
                out_loss[NG] = tot;
            }
            for (int g2 = 0; g2 < NG; g2++) g_loss_sum[g2] = 0.0;
            g_done = 0;
        }
    }
}

extern "C" void kernel_launch(void* const* d_in, const int* in_sizes, int n_in,
                              void* d_out, int out_size) {
    const float* feat = (const float*)d_in[0];
    const float* cb   = (const float*)d_in[1];
    if (n_in >= 2 && in_sizes[0] == NG * NK * ND) {
        const float* t = feat; feat = cb; cb = t;
    }
    float* out = (float*)d_out;

    const long long q_elems   = (long long)NG * NB * ND;
    const long long idx_elems = (long long)NG * NB;
    const long long full_sz   = q_elems + NG + 1 + idx_elems;
    const int write_q    = ((long long)out_size >= q_elems);
    const int write_loss = ((long long)out_size >= q_elems + NG + 1);
    const int write_idx  = ((long long)out_size >= full_sz);

    const int smem_bytes = NK * 32 * 4 + NK * 4 + 32;   // 67,616 B
    cudaFuncSetAttribute(vq_h2r2b_kernel,
                         cudaFuncAttributeMaxDynamicSharedMemorySize, smem_bytes);

    dim3 grid(XBLK, NG);
    float* out_loss = out + q_elems;
    float* out_idx  = out + q_elems + NG + 1;
    vq_h2r2b_kernel<<<grid, CTA, smem_bytes>>>(feat, cb, out, out_loss, out_idx,
                                               write_q, write_loss, write_idx);
}

// round 17
// speedup vs baseline: 1.2439x; 1.2203x over previous
#include <cuda_runtime.h>
#include <cuda_fp16.h>
#include <cstdint>
#include <float.h>

#define NG 5
#define NB 131072
#define NK 512
#define ND 64
#define CTA 256
#define XBLK (NB / CTA)          // 512 (1 row per thread)
#define NCTAS (NG * XBLK)        // 2560
#define SC2 0.00390625f          // 2/512

__device__ double g_loss_sum[NG];
__device__ unsigned int g_done = 0;

__device__ __forceinline__ __half2 H2(uint32_t u) { return *(__half2*)&u; }
__device__ __forceinline__ float PACK(float s, int k) {
    return __uint_as_float((__float_as_uint(s) & 0xFFFFFE00u) | (uint32_t)k);
}

// Exact distance: validated fp32 sequential-d fma chain (x from global/L1)
__device__ __forceinline__ float exact_dist(const float4* __restrict__ xr,
                                            const float4* __restrict__ ck,
                                            float xsq, float esqk) {
    float cr = 0.f;
    #pragma unroll
    for (int i = 0; i < 16; i++) {
        float4 v = ck[i];
        float4 x = xr[i];
        cr = fmaf(x.x, v.x, cr);
        cr = fmaf(x.y, v.y, cr);
        cr = fmaf(x.z, v.z, cr);
        cr = fmaf(x.w, v.w, cr);
    }
    return (xsq + esqk) - 2.0f * cr;
}

__global__ __launch_bounds__(CTA, 2) void vq_hp_kernel(
    const float* __restrict__ feat,   // [G,B,D]
    const float* __restrict__ cb,     // [G,K,D]
    float* __restrict__ out_q,        // [G,B,D]
    float* __restrict__ out_loss,     // [G+1]
    float* __restrict__ out_idx,      // [G,B] as float
    int write_q, int write_loss, int write_idx)
{
    extern __shared__ char smem[];
    uint32_t* cp  = (uint32_t*)smem;               // [512][32] half2 (512c_d,512c_{d+1})
    float*    esq = (float*)(smem + NK * 32 * 4);  // [512]
    float*    red = esq + NK;                      // [8]

    const int tid = threadIdx.x;
    const int g = blockIdx.y;
    const float* cbg = cb + (size_t)g * NK * ND;
    const size_t gNB = (size_t)g * NB;

    // ---- Stage codebook (2 cw/thread): half2 pairs of 512*c; exact e_sq ----
    #pragma unroll
    for (int s2 = 0; s2 < 2; s2++) {
        const int k = tid + s2 * CTA;
        const float4* cpg = (const float4*)(cbg + (size_t)k * ND);
        uint32_t* dst = cp + k * 32;
        float acc = 0.f;
        #pragma unroll
        for (int i = 0; i < 16; i++) {
            float4 v = cpg[i];
            acc = fmaf(v.x, v.x, acc);
            acc = fmaf(v.y, v.y, acc);
            acc = fmaf(v.z, v.z, acc);
            acc = fmaf(v.w, v.w, acc);
            __half2 h0 = __floats2half2_rn(v.x * 512.f, v.y * 512.f);
            __half2 h1 = __floats2half2_rn(v.z * 512.f, v.w * 512.f);
            dst[2 * i]     = *(uint32_t*)&h0;
            dst[2 * i + 1] = *(uint32_t*)&h1;
        }
        esq[k] = acc;
    }
    __syncthreads();

    // ---- Load row, pack (d,d+1) half2, exact x_sq (validated chain) ----
    const int row = blockIdx.x * CTA + tid;
    __half2 xh[32];
    float xsq = 0.f;
    {
        const float4* xp = (const float4*)(feat + (gNB + row) * ND);
        #pragma unroll
        for (int i = 0; i < 16; i++) {
            float4 a = xp[i];
            xsq = fmaf(a.x, a.x, xsq);
            xsq = fmaf(a.y, a.y, xsq);
            xsq = fmaf(a.z, a.z, xsq);
            xsq = fmaf(a.w, a.w, xsq);
            xh[2 * i]     = __floats2half2_rn(a.x, a.y);
            xh[2 * i + 1] = __floats2half2_rn(a.z, a.w);
        }
    }
    // statistical eps (R11-validated) + mantissa-packing margin (R12-validated)
    const float eps = 1.526e-5f * __fsqrt_rn(11.5f * xsq) + 1.8e-5f;

    // ---- HFMA2 filter with explicit ping-pong pipeline; packed top-3 ----
    float t0 = FLT_MAX, t1 = FLT_MAX, t2 = FLT_MAX;
    #define INS3(p)                                                            \
    if ((p) < t2) {                                                            \
        if ((p) < t0)      { t2 = t1; t1 = t0; t0 = (p); }                     \
        else if ((p) < t1) { t2 = t1; t1 = (p); }                              \
        else               { t2 = (p); }                                       \
    }
    // COMPUTE(U0..U3, base-dim h8): 16 HFMA2, dims h8*? -> uses xh[xo..xo+3]
    #define COMPUTE(U0, U1, U2, U3, XO)                                        \
    {                                                                          \
        __half2 x0 = xh[(XO) + 0], x1 = xh[(XO) + 1];                          \
        __half2 x2 = xh[(XO) + 2], x3 = xh[(XO) + 3];                          \
        a0 = __hfma2(H2((U0).x), x0, a0);                                      \
        a1 = __hfma2(H2((U1).x), x0, a1);                                      \
        a2 = __hfma2(H2((U2).x), x0, a2);                                      \
        a3 = __hfma2(H2((U3).x), x0, a3);                                      \
        a0 = __hfma2(H2((U0).y), x1, a0);                                      \
        a1 = __hfma2(H2((U1).y), x1, a1);                                      \
        a2 = __hfma2(H2((U2).y), x1, a2);                                      \
        a3 = __hfma2(H2((U3).y), x1, a3);                                      \
        a0 = __hfma2(H2((U0).z), x2, a0);                                      \
        a1 = __hfma2(H2((U1).z), x2, a1);                                      \
        a2 = __hfma2(H2((U2).z), x2, a2);                                      \
        a3 = __hfma2(H2((U3).z), x2, a3);                                      \
        a0 = __hfma2(H2((U0).w), x3, a0);                                      \
        a1 = __hfma2(H2((U1).w), x3, a1);                                      \
        a2 = __hfma2(H2((U2).w), x3, a2);                                      \
        a3 = __hfma2(H2((U3).w), x3, a3);                                      \
    }
    #define LOADU(DST0, DST1, DST2, DST3, BASE, C)                             \
        DST0 = *(const uint4*)((BASE) + 0 * 32 + (C) * 4);                     \
        DST1 = *(const uint4*)((BASE) + 1 * 32 + (C) * 4);                     \
        DST2 = *(const uint4*)((BASE) + 2 * 32 + (C) * 4);                     \
        DST3 = *(const uint4*)((BASE) + 3 * 32 + (C) * 4);

    uint4 u0, u1, u2, u3, v0, v1, v2, v3;
    LOADU(u0, u1, u2, u3, cp, 0)          // block 0, c=0
    #pragma unroll 1
    for (int kb = 0; kb < NK / 4; kb++) {
        const int k0 = kb * 4;
        const uint32_t* pcur  = cp + (size_t)k0 * 32;
        const uint32_t* pnext = cp + (size_t)(((kb + 1) & 127) * 4) * 32;
        __half2 z = __float2half2_rn(0.f);
        __half2 a0 = z, a1 = z, a2 = z, a3 = z;
        #pragma unroll
        for (int h = 0; h < 4; h++) {
            // v <- c = 2h+1 ; compute with u (c = 2h)
            LOADU(v0, v1, v2, v3, pcur, 2 * h + 1)
            COMPUTE(u0, u1, u2, u3, 8 * h)
            // u <- c = 2h+2 (or next block c=0) ; compute with v (c = 2h+1)
            if (h < 3) {
                LOADU(u0, u1, u2, u3, pcur, 2 * h + 2)
            } else {
                LOADU(u0, u1, u2, u3, pnext, 0)
            }
            COMPUTE(v0, v1, v2, v3, 8 * h + 4)
        }
        float s, p;
        s = fmaf(-(__low2float(a0) + __high2float(a0)), SC2, esq[k0 + 0]);
        p = PACK(s, k0 + 0); INS3(p)
        s = fmaf(-(__low2float(a1) + __high2float(a1)), SC2, esq[k0 + 1]);
        p = PACK(s, k0 + 1); INS3(p)
        s = fmaf(-(__low2float(a2) + __high2float(a2)), SC2, esq[k0 + 2]);
        p = PACK(s, k0 + 2); INS3(p)
        s = fmaf(-(__low2float(a3) + __high2float(a3)), SC2, esq[k0 + 3]);
        p = PACK(s, k0 + 3); INS3(p)
    }
    #undef LOADU
    #undef COMPUTE
    #undef INS3

    // ---- Selection (x reloaded from global; L1-hot) ----
    const float4* xr = (const float4*)(feat + (gNB + row) * ND);
    int bk = (int)(__float_as_uint(t0) & 511u);
    const float th = t0 + eps;
    if (t1 <= th) {
        if (t2 <= th) {
            // provable overflow: full exact scan (rare)
            float best = FLT_MAX;
            bk = 0;
            for (int k = 0; k < NK; k++) {
                float dk = exact_dist(xr, (const float4*)(cbg + (size_t)k * ND),
                                      xsq, esq[k]);
                if (dk < best || (dk == best && k < bk)) { best = dk; bk = k; }
            }
        } else {
            const int ka  = (int)(__float_as_uint(t0) & 511u);
            const int kb2 = (int)(__float_as_uint(t1) & 511u);
            float da = exact_dist(xr, (const float4*)(cbg + (size_t)ka * ND),
                                  xsq, esq[ka]);
            float db = exact_dist(xr, (const float4*)(cbg + (size_t)kb2 * ND),
                                  xsq, esq[kb2]);
            // reference first-min tie-break
            if (db < da || (db == da && kb2 < ka)) bk = kb2; else bk = ka;
        }
    }

    // ---- Outputs: quantized_st = x + (q - x), index, loss partial ----
    float lsum = 0.f;
    {
        const float4* qp = (const float4*)(cbg + (size_t)bk * ND);
        float4* oq = (float4*)(out_q + (gNB + row) * ND);
        #pragma unroll
        for (int i = 0; i < 16; i++) {
            float4 qv = qp[i], fv = xr[i];
            float dx0 = qv.x - fv.x, dx1 = qv.y - fv.y;
            float dx2 = qv.z - fv.z, dx3 = qv.w - fv.w;
            lsum = fmaf(dx0, dx0, lsum);
            lsum = fmaf(dx1, dx1, lsum);
            lsum = fmaf(dx2, dx2, lsum);
            lsum = fmaf(dx3, dx3, lsum);
            if (write_q)
                oq[i] = make_float4(fv.x + dx0, fv.y + dx1, fv.z + dx2, fv.w + dx3);
        }
    }
    if (write_idx) out_idx[gNB + row] = (float)bk;

    // ---- Loss: warp shuffle -> shared -> double atomic; last CTA finalizes ----
    #pragma unroll
    for (int off = 16; off > 0; off >>= 1)
        lsum += __shfl_xor_sync(0xFFFFFFFFu, lsum, off);
    if ((tid & 31) == 0) red[tid >> 5] = lsum;
    __syncthreads();
    if (tid == 0) {
        double s = 0.0;
        #pragma unroll
        for (int w = 0; w < CTA / 32; w++) s += (double)red[w];
        atomicAdd(&g_loss_sum[g], s);
        __threadfence();
        unsigned int t = atomicAdd(&g_done, 1u);
        if (t == NCTAS - 1) {
            __threadfence();
            if (write_loss) {
                const double inv = 1.25 / ((double)NB * (double)ND);
                float tot = 0.f;
                for (int g2 = 0; g2 < NG; g2++) {
                    float pl = (float)(g_loss_sum[g2] * inv);
                    out_loss[g2] = pl;
                    tot += pl;
                }
                out_loss[NG] = tot;
            }
            for (int g2 = 0; g2 < NG; g2++) g_loss_sum[g2] = 0.0;
            g_done = 0;
        }
    }
}

extern "C" void kernel_launch(void* const* d_in, const int* in_sizes, int n_in,
                              void* d_out, int out_size) {
    const float* feat = (const float*)d_in[0];
    const float* cb   = (const float*)d_in[1];
    if (n_in >= 2 && in_sizes[0] == NG * NK * ND) {
        const float* t = feat; feat = cb; cb = t;
    }
    float* out = (float*)d_out;

    const long long q_elems   = (long long)NG * NB * ND;
    const long long idx_elems = (long long)NG * NB;
    const long long full_sz   = q_elems + NG + 1 + idx_elems;
    const int write_q    = ((long long)out_size >= q_elems);
    const int write_loss = ((long long)out_size >= q_elems + NG + 1);
    const int write_idx  = ((long long)out_size >= full_sz);

    const int smem_bytes = NK * 32 * 4 + NK * 4 + 32;   // 67,616 B -> 2 CTAs/SM
    cudaFuncSetAttribute(vq_hp_kernel,
                         cudaFuncAttributeMaxDynamicSharedMemorySize, smem_bytes);

    dim3 grid(XBLK, NG);
    float* out_loss = out + q_elems;
    float* out_idx  = out + q_elems + NG + 1;
    vq_hp_kernel<<<grid, CTA, smem_bytes>>>(feat, cb, out, out_loss, out_idx,
                                            write_q, write_loss, write_idx);
}